// round 16
// baseline (speedup 1.0000x reference)
#include <cuda_runtime.h>
#include <cuda_fp16.h>
#include <cstdint>

#define HW 128
#define CH 128
#define NB 8

// ---------------------------------------------------------------------------
// Device-global scratch
// ---------------------------------------------------------------------------
__device__ __align__(256) __half d_x16[(size_t)NB * HW * HW * CH];  // NHWC fp16
// Winograd weights, native n8 B-fragment order:
// [cg 8][nu 16][group 16][lane 32] x uint2
__device__ __align__(256) uint32_t d_WU[8 * 16 * 16 * 64];          // 512KB
__device__ float d_Beff[128];

__constant__ int cJ[8][8] = {
  {0,1,2,3,4,5,6,7},{1,0,4,6,2,7,3,5},{2,4,0,5,1,3,7,6},{3,6,5,0,7,2,1,4},
  {4,2,1,7,0,6,5,3},{5,7,3,2,6,0,4,1},{6,3,7,1,5,4,0,2},{7,5,6,4,3,1,2,0}};
__constant__ float cS[8][8] = {
  { 1, 1, 1, 1,-1,-1,-1,-1},{ 1, 1,-1,-1, 1,-1, 1,-1},
  { 1, 1, 1,-1,-1, 1, 1, 1},{ 1, 1, 1, 1,-1,-1,-1,-1},
  { 1, 1,-1, 1, 1, 1,-1, 1},{ 1, 1, 1,-1,-1, 1, 1, 1},
  { 1, 1,-1,-1, 1,-1, 1,-1},{ 1, 1,-1, 1, 1, 1,-1, 1}};

__device__ __forceinline__ uint32_t smem_u32(const void* p) {
  uint32_t a;
  asm("{ .reg .u64 t; cvta.to.shared.u64 t, %1; cvt.u32.u64 %0, t; }"
      : "=r"(a) : "l"(p));
  return a;
}
__device__ __forceinline__ void cp16(uint32_t dst, const void* src) {
  asm volatile("cp.async.cg.shared.global [%0], [%1], 16;"
               :: "r"(dst), "l"(src) : "memory");
}
__device__ __forceinline__ void cp_commit() {
  asm volatile("cp.async.commit_group;" ::: "memory");
}
__device__ __forceinline__ void cp_wait1() {
  asm volatile("cp.async.wait_group 1;" ::: "memory");
}
__device__ __forceinline__ void cp_wait0() {
  asm volatile("cp.async.wait_group 0;" ::: "memory");
}

// Profiler-alignment no-op (keeps conv on the ncu-profiled launch index).
__global__ void nop_kernel() {}

// ---------------------------------------------------------------------------
// Prepass 1: fp32 NCHW -> fp16 NHWC. Two ci-half passes, 34.5KB smem,
// 6 CTAs/SM. (unchanged from round 15 — measured ~13us)
// ---------------------------------------------------------------------------
#define XS1 132
#define XS2 72

__global__ void __launch_bounds__(256) xprep_kernel(const float* __restrict__ x) {
  __shared__ __align__(16) __half sm1[64 * XS1];
  __shared__ __align__(16) __half sm2[128 * XS2];
  const int h = blockIdx.x, b = blockIdx.y, tid = threadIdx.x;
  __half* op = d_x16 + ((size_t)(b * HW + h)) * HW * CH;

#pragma unroll
  for (int p = 0; p < 2; ++p) {
    const float* xp = x + ((size_t)(b * CH + p * 64)) * HW * HW + (size_t)h * HW;

#pragma unroll
    for (int i = 0; i < 2; ++i) {
      int t = tid + i * 256;
      int cil = t >> 3, seg = t & 7;
      const float4* src = (const float4*)(xp + (size_t)cil * HW * HW + seg * 16);
      float4 v0 = src[0], v1 = src[1], v2 = src[2], v3 = src[3];
      __half2* dst = (__half2*)(sm1 + cil * XS1 + seg * 16);
      dst[0] = __floats2half2_rn(v0.x, v0.y);
      dst[1] = __floats2half2_rn(v0.z, v0.w);
      dst[2] = __floats2half2_rn(v1.x, v1.y);
      dst[3] = __floats2half2_rn(v1.z, v1.w);
      dst[4] = __floats2half2_rn(v2.x, v2.y);
      dst[5] = __floats2half2_rn(v2.z, v2.w);
      dst[6] = __floats2half2_rn(v3.x, v3.y);
      dst[7] = __floats2half2_rn(v3.z, v3.w);
    }
    __syncthreads();

#pragma unroll
    for (int i = 0; i < 2; ++i) {
      int t = tid + i * 256;
      int w2 = (t & 7) | (((t >> 5) & 7) << 3);
      int c8l = ((t >> 3) & 3) | ((t >> 8) << 2);
      int w = w2 * 2;
      __half lo[8], hi[8];
#pragma unroll
      for (int jj = 0; jj < 8; ++jj) {
        uint32_t v = *(const uint32_t*)(sm1 + (c8l * 8 + jj) * XS1 + w);
        lo[jj] = __ushort_as_half((unsigned short)(v & 0xFFFF));
        hi[jj] = __ushort_as_half((unsigned short)(v >> 16));
      }
      *(uint4*)(sm2 + (size_t)w * XS2 + c8l * 8)       = *(const uint4*)lo;
      *(uint4*)(sm2 + (size_t)(w + 1) * XS2 + c8l * 8) = *(const uint4*)hi;
    }
    __syncthreads();

#pragma unroll
    for (int i = 0; i < 4; ++i) {
      int t = tid + i * 256;
      int c8l = t & 7, w = t >> 3;
      uint4 u = *(const uint4*)(sm2 + (size_t)w * XS2 + c8l * 8);
      *(uint4*)(op + (size_t)w * CH + p * 64 + c8l * 8) = u;
    }
    __syncthreads();
  }
}

// ---------------------------------------------------------------------------
// Prepass 2: GA3-fold + Winograd weight transform -> n8-fragment order; bias.
// ---------------------------------------------------------------------------
__global__ void __launch_bounds__(256)
wu_kernel(const float* __restrict__ W, const float* __restrict__ bia) {
  int t = blockIdx.x * 256 + threadIdx.x;
  if (blockIdx.x == 0 && threadIdx.x < 128) {
    int co = threadIdx.x, cout = co >> 3, m = co & 7;
    float s = 0.f;
#pragma unroll
    for (int k = 0; k < 8; k++) s += cS[m][k] * bia[cJ[m][k] * 16 + cout];
    d_Beff[co] = s;
  }
  if (t >= 128 * 64) return;
  int co = t >> 6, cp = t & 63;
  int m = co & 7, cout = co >> 3;

  float U2[2][16];
#pragma unroll
  for (int s2 = 0; s2 < 2; ++s2) {
    int ci = cp * 2 + s2;
    int cin = ci >> 3, k = ci & 7;
    float sg = cS[m][k];
    const float* wp = W + ((cJ[m][k] * 16 + cout) * 16 + cin) * 9;
    float w[3][3];
#pragma unroll
    for (int r = 0; r < 3; ++r)
#pragma unroll
      for (int c = 0; c < 3; ++c) w[r][c] = sg * wp[r * 3 + c];
    float Gw[4][3];
#pragma unroll
    for (int c = 0; c < 3; ++c) {
      Gw[0][c] = w[0][c];
      Gw[1][c] = 0.5f * (w[0][c] + w[1][c] + w[2][c]);
      Gw[2][c] = 0.5f * (w[0][c] - w[1][c] + w[2][c]);
      Gw[3][c] = w[2][c];
    }
#pragma unroll
    for (int i = 0; i < 4; ++i) {
      U2[s2][i * 4 + 0] = Gw[i][0];
      U2[s2][i * 4 + 1] = 0.5f * (Gw[i][0] + Gw[i][1] + Gw[i][2]);
      U2[s2][i * 4 + 2] = 0.5f * (Gw[i][0] - Gw[i][1] + Gw[i][2]);
      U2[s2][i * 4 + 3] = Gw[i][2];
    }
  }
  int cg = cp >> 3;
  int kk = cp & 7;
  int reg = kk >> 2;
  int lane = (co & 7) * 4 + (kk & 3);
  int group = co >> 3;
#pragma unroll
  for (int nu = 0; nu < 16; ++nu) {
    __half2 hv = __floats2half2_rn(U2[0][nu], U2[1][nu]);
    d_WU[(((cg * 16 + nu) * 16 + group) * 32 + lane) * 2 + reg] =
        *(uint32_t*)&hv;
  }
}

// ---------------------------------------------------------------------------
// Winograd conv, co-split. CTA per (b, tile-row, w-half, co-half):
// 32 tiles x 64 co, K=128 ci in 4 chunks of 32. 8 warps = m32 x n8 each.
// ~80 regs + 73KB smem -> THREE CTAs per SM (24 warps): latency hiding.
// A staging + transform duplicated across the two co-half CTAs (accepted).
// ---------------------------------------------------------------------------
#define A_SLOT 64
#define A_NSLOT 66
#define A_BYTES (4 * A_NSLOT * A_SLOT)   // 16896
#define V_STR 80
#define V_BYTES (16 * 32 * V_STR)        // 40960
#define SM_TOTAL (2 * A_BYTES + V_BYTES) // 74752
#define NTHR 256

__global__ void __launch_bounds__(NTHR, 3)
conv_wino(float* __restrict__ out) {
  extern __shared__ __align__(128) unsigned char sh[];
  const uint32_t sA0 = smem_u32(sh);
  const uint32_t sV  = sA0 + 2 * A_BYTES;

  const int tid = threadIdx.x, warp = tid >> 5, lane = tid & 31;
  const int bx = blockIdx.x, b = blockIdx.y;
  const int th = bx >> 2, wh = (bx >> 1) & 1, chh = bx & 1;
  const int h0 = th * 2;
  const int w0 = wh * 64;
  const int g8 = chh * 8 + warp;          // W group index (co>>3)
  const int g = lane >> 2, q = lane & 3;
  const int rsel = lane & 15, csel = lane >> 4;

  {
    uint4 z = make_uint4(0, 0, 0, 0);
    uint4* p = (uint4*)sh;
    for (int i = tid; i < 2 * A_BYTES / 16; i += NTHR) p[i] = z;
  }
  __syncthreads();

  // [mblk][gi][ji][xx*2+yy]
  float outacc[2][2][2][4];
#pragma unroll
  for (int i0 = 0; i0 < 2; ++i0)
#pragma unroll
    for (int i1 = 0; i1 < 2; ++i1)
#pragma unroll
      for (int i2 = 0; i2 < 2; ++i2)
#pragma unroll
        for (int i3 = 0; i3 < 4; ++i3) outacc[i0][i1][i2][i3] = 0.f;

  // stage 32-ci chunk: 1056 tasks = (r 4, slot 66, seg 4 of 16B)
  auto issueA = [&](int c, int buf) {
    uint32_t aB = sA0 + buf * A_BYTES;
#pragma unroll
    for (int i = 0; i < 5; ++i) {
      int task = tid + i * NTHR;
      if (task < 4 * A_NSLOT * 4) {
        int seg = task & 3;
        int s = (task >> 2) % A_NSLOT;
        int r = (task >> 2) / A_NSLOT;
        int gh = h0 - 1 + r;
        int w = w0 + s - 1;
        if ((unsigned)gh < (unsigned)HW && (unsigned)w < (unsigned)HW) {
          const __half* src = d_x16 +
              (((size_t)(b * HW + gh) * HW + w) * CH + c * 32 + seg * 8);
          cp16(aB + (uint32_t)(r * A_NSLOT + s) * A_SLOT + seg * 16, src);
        }
      }
    }
    cp_commit();
  };

  // transform: 512 items = (tw 0..31, cp 0..15), 2 per thread
  auto transform = [&](int buf) {
    const unsigned char* aB = sh + buf * A_BYTES;
#pragma unroll
    for (int it = 0; it < 2; ++it) {
      int item = tid + it * NTHR;
      int cp = item & 15;
      int tw = item >> 4;
      const unsigned char* base = aB + (uint32_t)(2 * tw) * A_SLOT + cp * 4;
      __half2 te[4][4];
#pragma unroll
      for (int j = 0; j < 4; ++j) {
        __half2 d0 = *(const __half2*)(base + (uint32_t)(0 * A_NSLOT + j) * A_SLOT);
        __half2 d1 = *(const __half2*)(base + (uint32_t)(1 * A_NSLOT + j) * A_SLOT);
        __half2 d2 = *(const __half2*)(base + (uint32_t)(2 * A_NSLOT + j) * A_SLOT);
        __half2 d3 = *(const __half2*)(base + (uint32_t)(3 * A_NSLOT + j) * A_SLOT);
        te[0][j] = __hsub2(d0, d2);
        te[1][j] = __hadd2(d1, d2);
        te[2][j] = __hsub2(d2, d1);
        te[3][j] = __hsub2(d1, d3);
      }
#pragma unroll
      for (int i2 = 0; i2 < 4; ++i2) {
        __half2 v0 = __hsub2(te[i2][0], te[i2][2]);
        __half2 v1 = __hadd2(te[i2][1], te[i2][2]);
        __half2 v2 = __hsub2(te[i2][2], te[i2][1]);
        __half2 v3 = __hsub2(te[i2][1], te[i2][3]);
        uint32_t vb = (uint32_t)((i2 * 4) * 32 + tw) * V_STR + cp * 4;
        *(__half2*)(sh + 2 * A_BYTES + vb)                 = v0;
        *(__half2*)(sh + 2 * A_BYTES + vb + 32 * V_STR)    = v1;
        *(__half2*)(sh + 2 * A_BYTES + vb + 2 * 32 * V_STR) = v2;
        *(__half2*)(sh + 2 * A_BYTES + vb + 3 * 32 * V_STR) = v3;
      }
    }
  };

  auto ldW = [&](int cg, int nu) -> uint2 {
    return *((const uint2*)d_WU + (((cg * 16 + nu) * 16 + g8) * 32 + lane));
  };

  const float AT0[4] = {1.f, 1.f, 1.f, 0.f};
  const float AT1[4] = {0.f, 1.f, -1.f, -1.f};
  const float fz = 0.f;

  issueA(0, 0);

  for (int c = 0; c < 4; ++c) {
    if (c < 3) issueA(c + 1, (c + 1) & 1);
    if (c < 3) cp_wait1(); else cp_wait0();
    __syncthreads();

    transform(c & 1);
    __syncthreads();

    uint2 wc = ldW(c * 2, 0);
    uint2 wn;

#pragma unroll
    for (int nu = 0; nu < 16; ++nu) {
      float macc[2][4];
#pragma unroll
      for (int sub = 0; sub < 2; ++sub) {
        int ns = nu * 2 + sub;
        if (ns < 31) {
          int nn = ns + 1;
          wn = ldW(c * 2 + (nn & 1), nn >> 1);
        }

        uint32_t afr[2][4];
#pragma unroll
        for (int mblk = 0; mblk < 2; ++mblk) {
          uint32_t addr = sV +
              (uint32_t)(nu * 32 + mblk * 16 + rsel) * V_STR
              + sub * 32 + csel * 16;
          asm volatile(
            "ldmatrix.sync.aligned.m8n8.x4.shared.b16 {%0,%1,%2,%3}, [%4];\n"
            : "=r"(afr[mblk][0]), "=r"(afr[mblk][1]),
              "=r"(afr[mblk][2]), "=r"(afr[mblk][3])
            : "r"(addr));
        }

#pragma unroll
        for (int mblk = 0; mblk < 2; ++mblk) {
          if (sub == 0)
            asm volatile(
              "mma.sync.aligned.m16n8k16.row.col.f32.f16.f16.f32 "
              "{%0,%1,%2,%3}, {%4,%5,%6,%7}, {%8,%9}, {%10,%10,%10,%10};\n"
              : "=f"(macc[mblk][0]), "=f"(macc[mblk][1]),
                "=f"(macc[mblk][2]), "=f"(macc[mblk][3])
              : "r"(afr[mblk][0]), "r"(afr[mblk][1]),
                "r"(afr[mblk][2]), "r"(afr[mblk][3]),
              "r"(wc.x), "r"(wc.y), "f"(fz));
          else
            asm volatile(
              "mma.sync.aligned.m16n8k16.row.col.f32.f16.f16.f32 "
              "{%0,%1,%2,%3}, {%4,%5,%6,%7}, {%8,%9}, {%0,%1,%2,%3};\n"
              : "+f"(macc[mblk][0]), "+f"(macc[mblk][1]),
                "+f"(macc[mblk][2]), "+f"(macc[mblk][3])
              : "r"(afr[mblk][0]), "r"(afr[mblk][1]),
                "r"(afr[mblk][2]), "r"(afr[mblk][3]),
                "r"(wc.x), "r"(wc.y));
        }
        if (ns < 31) wc = wn;
      }

      // fold once per nu per chunk
      const int nur = nu >> 2, nuc = nu & 3;
#pragma unroll
      for (int mblk = 0; mblk < 2; ++mblk)
#pragma unroll
        for (int gi = 0; gi < 2; ++gi)
#pragma unroll
          for (int ji = 0; ji < 2; ++ji) {
            float mval = macc[mblk][gi * 2 + ji];
#pragma unroll
            for (int xx = 0; xx < 2; ++xx) {
              float cx = (xx == 0) ? AT0[nur] : AT1[nur];
              if (cx == 0.f) continue;
#pragma unroll
              for (int yy = 0; yy < 2; ++yy) {
                float cy = (yy == 0) ? AT0[nuc] : AT1[nuc];
                if (cy == 0.f) continue;
                outacc[mblk][gi][ji][xx * 2 + yy] += (cx * cy) * mval;
              }
            }
          }
    }
  }

  // ---- epilogue: bias + float2 stores ----
#pragma unroll
  for (int ji = 0; ji < 2; ++ji) {
    int co = g8 * 8 + 2 * q + ji;
    float be = d_Beff[co];
    float* ob = out + ((size_t)(b * CH + co)) * HW * HW;
#pragma unroll
    for (int mblk = 0; mblk < 2; ++mblk)
#pragma unroll
      for (int gi = 0; gi < 2; ++gi) {
        int twp = mblk * 16 + g + gi * 8;
        int wpix = w0 + 2 * twp;
#pragma unroll
        for (int xx = 0; xx < 2; ++xx) {
          float2 v;
          v.x = outacc[mblk][gi][ji][xx * 2 + 0] + be;
          v.y = outacc[mblk][gi][ji][xx * 2 + 1] + be;
          *(float2*)(ob + (size_t)(h0 + xx) * HW + wpix) = v;
        }
      }
  }
}

// ---------------------------------------------------------------------------
extern "C" void kernel_launch(void* const* d_in, const int* in_sizes, int n_in,
                              void* d_out, int out_size) {
  (void)in_sizes; (void)n_in; (void)out_size;
  const float* x = (const float*)d_in[0];
  const float* W = (const float*)d_in[1];
  const float* b = (const float*)d_in[2];
  float* out = (float*)d_out;

  dim3 gx(HW, NB);
  xprep_kernel<<<gx, 256>>>(x);
  wu_kernel<<<32, 256>>>(W, b);
  nop_kernel<<<1, 32>>>();   // profiler alignment: conv = launch position 3

  cudaFuncSetAttribute(conv_wino,
                       cudaFuncAttributeMaxDynamicSharedMemorySize, SM_TOTAL);
  dim3 grid(256, NB);   // (tile-row * w-half * co-half, b)
  conv_wino<<<grid, NTHR, SM_TOTAL>>>(out);
}

// round 17
// speedup vs baseline: 1.3387x; 1.3387x over previous
#include <cuda_runtime.h>
#include <cuda_fp16.h>
#include <cstdint>

#define HW 128
#define CH 128
#define NB 8

// ---------------------------------------------------------------------------
// Device-global scratch
// ---------------------------------------------------------------------------
__device__ __align__(256) __half d_x16[(size_t)NB * HW * HW * CH];  // NHWC fp16
// Winograd weights, native n8 B-fragment order:
// [cg 8][nu 16][group 16][lane 32] x uint2
__device__ __align__(256) uint32_t d_WU[8 * 16 * 16 * 64];          // 512KB
__device__ float d_Beff[128];

__constant__ int cJ[8][8] = {
  {0,1,2,3,4,5,6,7},{1,0,4,6,2,7,3,5},{2,4,0,5,1,3,7,6},{3,6,5,0,7,2,1,4},
  {4,2,1,7,0,6,5,3},{5,7,3,2,6,0,4,1},{6,3,7,1,5,4,0,2},{7,5,6,4,3,1,2,0}};
__constant__ float cS[8][8] = {
  { 1, 1, 1, 1,-1,-1,-1,-1},{ 1, 1,-1,-1, 1,-1, 1,-1},
  { 1, 1, 1,-1,-1, 1, 1, 1},{ 1, 1, 1, 1,-1,-1,-1,-1},
  { 1, 1,-1, 1, 1, 1,-1, 1},{ 1, 1, 1,-1,-1, 1, 1, 1},
  { 1, 1,-1,-1, 1,-1, 1,-1},{ 1, 1,-1, 1, 1, 1,-1, 1}};

__device__ __forceinline__ uint32_t smem_u32(const void* p) {
  uint32_t a;
  asm("{ .reg .u64 t; cvta.to.shared.u64 t, %1; cvt.u32.u64 %0, t; }"
      : "=r"(a) : "l"(p));
  return a;
}
__device__ __forceinline__ void cp16(uint32_t dst, const void* src) {
  asm volatile("cp.async.cg.shared.global [%0], [%1], 16;"
               :: "r"(dst), "l"(src) : "memory");
}
__device__ __forceinline__ void cp_commit() {
  asm volatile("cp.async.commit_group;" ::: "memory");
}
__device__ __forceinline__ void cp_wait1() {
  asm volatile("cp.async.wait_group 1;" ::: "memory");
}
__device__ __forceinline__ void cp_wait0() {
  asm volatile("cp.async.wait_group 0;" ::: "memory");
}

// Profiler-alignment no-op (keeps conv on the ncu-profiled launch index).
__global__ void nop_kernel() {}

// ---------------------------------------------------------------------------
// Prepass 1: fp32 NCHW -> fp16 NHWC. Two ci-half passes, 34.5KB smem.
// ---------------------------------------------------------------------------
#define XS1 132
#define XS2 72

__global__ void __launch_bounds__(256) xprep_kernel(const float* __restrict__ x) {
  __shared__ __align__(16) __half sm1[64 * XS1];
  __shared__ __align__(16) __half sm2[128 * XS2];
  const int h = blockIdx.x, b = blockIdx.y, tid = threadIdx.x;
  __half* op = d_x16 + ((size_t)(b * HW + h)) * HW * CH;

#pragma unroll
  for (int p = 0; p < 2; ++p) {
    const float* xp = x + ((size_t)(b * CH + p * 64)) * HW * HW + (size_t)h * HW;

#pragma unroll
    for (int i = 0; i < 2; ++i) {
      int t = tid + i * 256;
      int cil = t >> 3, seg = t & 7;
      const float4* src = (const float4*)(xp + (size_t)cil * HW * HW + seg * 16);
      float4 v0 = src[0], v1 = src[1], v2 = src[2], v3 = src[3];
      __half2* dst = (__half2*)(sm1 + cil * XS1 + seg * 16);
      dst[0] = __floats2half2_rn(v0.x, v0.y);
      dst[1] = __floats2half2_rn(v0.z, v0.w);
      dst[2] = __floats2half2_rn(v1.x, v1.y);
      dst[3] = __floats2half2_rn(v1.z, v1.w);
      dst[4] = __floats2half2_rn(v2.x, v2.y);
      dst[5] = __floats2half2_rn(v2.z, v2.w);
      dst[6] = __floats2half2_rn(v3.x, v3.y);
      dst[7] = __floats2half2_rn(v3.z, v3.w);
    }
    __syncthreads();

#pragma unroll
    for (int i = 0; i < 2; ++i) {
      int t = tid + i * 256;
      int w2 = (t & 7) | (((t >> 5) & 7) << 3);
      int c8l = ((t >> 3) & 3) | ((t >> 8) << 2);
      int w = w2 * 2;
      __half lo[8], hi[8];
#pragma unroll
      for (int jj = 0; jj < 8; ++jj) {
        uint32_t v = *(const uint32_t*)(sm1 + (c8l * 8 + jj) * XS1 + w);
        lo[jj] = __ushort_as_half((unsigned short)(v & 0xFFFF));
        hi[jj] = __ushort_as_half((unsigned short)(v >> 16));
      }
      *(uint4*)(sm2 + (size_t)w * XS2 + c8l * 8)       = *(const uint4*)lo;
      *(uint4*)(sm2 + (size_t)(w + 1) * XS2 + c8l * 8) = *(const uint4*)hi;
    }
    __syncthreads();

#pragma unroll
    for (int i = 0; i < 4; ++i) {
      int t = tid + i * 256;
      int c8l = t & 7, w = t >> 3;
      uint4 u = *(const uint4*)(sm2 + (size_t)w * XS2 + c8l * 8);
      *(uint4*)(op + (size_t)w * CH + p * 64 + c8l * 8) = u;
    }
    __syncthreads();
  }
}

// ---------------------------------------------------------------------------
// Prepass 2: GA3-fold + Winograd weight transform -> n8-fragment order; bias.
// ---------------------------------------------------------------------------
__global__ void __launch_bounds__(256)
wu_kernel(const float* __restrict__ W, const float* __restrict__ bia) {
  int t = blockIdx.x * 256 + threadIdx.x;
  if (blockIdx.x == 0 && threadIdx.x < 128) {
    int co = threadIdx.x, cout = co >> 3, m = co & 7;
    float s = 0.f;
#pragma unroll
    for (int k = 0; k < 8; k++) s += cS[m][k] * bia[cJ[m][k] * 16 + cout];
    d_Beff[co] = s;
  }
  if (t >= 128 * 64) return;
  int co = t >> 6, cp = t & 63;
  int m = co & 7, cout = co >> 3;

  float U2[2][16];
#pragma unroll
  for (int s2 = 0; s2 < 2; ++s2) {
    int ci = cp * 2 + s2;
    int cin = ci >> 3, k = ci & 7;
    float sg = cS[m][k];
    const float* wp = W + ((cJ[m][k] * 16 + cout) * 16 + cin) * 9;
    float w[3][3];
#pragma unroll
    for (int r = 0; r < 3; ++r)
#pragma unroll
      for (int c = 0; c < 3; ++c) w[r][c] = sg * wp[r * 3 + c];
    float Gw[4][3];
#pragma unroll
    for (int c = 0; c < 3; ++c) {
      Gw[0][c] = w[0][c];
      Gw[1][c] = 0.5f * (w[0][c] + w[1][c] + w[2][c]);
      Gw[2][c] = 0.5f * (w[0][c] - w[1][c] + w[2][c]);
      Gw[3][c] = w[2][c];
    }
#pragma unroll
    for (int i = 0; i < 4; ++i) {
      U2[s2][i * 4 + 0] = Gw[i][0];
      U2[s2][i * 4 + 1] = 0.5f * (Gw[i][0] + Gw[i][1] + Gw[i][2]);
      U2[s2][i * 4 + 2] = 0.5f * (Gw[i][0] - Gw[i][1] + Gw[i][2]);
      U2[s2][i * 4 + 3] = Gw[i][2];
    }
  }
  int cg = cp >> 3;
  int kk = cp & 7;
  int reg = kk >> 2;
  int lane = (co & 7) * 4 + (kk & 3);
  int group = co >> 3;
#pragma unroll
  for (int nu = 0; nu < 16; ++nu) {
    __half2 hv = __floats2half2_rn(U2[0][nu], U2[1][nu]);
    d_WU[(((cg * 16 + nu) * 16 + group) * 32 + lane) * 2 + reg] =
        *(uint32_t*)&hv;
  }
}

// ---------------------------------------------------------------------------
// Winograd conv (round-15 structure: 256-thread CTA per (b, tile-row,
// w-half), 8 warps m32 x n16, 2 CTAs/SM). NEW: fold uses packed
// fma.rn.f32x2 (FFMA2) with co-paired accumulators: fold instr -28%,
// fma-pipe cycles -50%.
// ---------------------------------------------------------------------------
#define A_SLOT 96
#define A_NSLOT 66
#define A_BYTES (4 * A_NSLOT * A_SLOT)   // 25344
#define V_STR 80
#define V_BYTES (16 * 32 * V_STR)        // 40960
#define SM_TOTAL (2 * A_BYTES + V_BYTES) // 91648
#define NTHR 256

__global__ void __launch_bounds__(NTHR, 2)
conv_wino(float* __restrict__ out) {
  extern __shared__ __align__(128) unsigned char sh[];
  const uint32_t sA0 = smem_u32(sh);
  const uint32_t sV  = sA0 + 2 * A_BYTES;

  const int tid = threadIdx.x, warp = tid >> 5, lane = tid & 31;
  const int th = blockIdx.x >> 1, wh = blockIdx.x & 1, b = blockIdx.y;
  const int h0 = th * 2;
  const int w0 = wh * 64;
  const int wN8 = warp;
  const int g = lane >> 2, q = lane & 3;
  const int rsel = lane & 15, csel = lane >> 4;

  {
    uint4 z = make_uint4(0, 0, 0, 0);
    uint4* p = (uint4*)sh;
    for (int i = tid; i < 2 * A_BYTES / 16; i += NTHR) p[i] = z;
  }
  __syncthreads();

  // Packed output accumulators: pair over ji (adjacent co).
  // po[mblk][grp][gi][xx*2+yy]
  unsigned long long po[2][2][2][4];
#pragma unroll
  for (int i0 = 0; i0 < 2; ++i0)
#pragma unroll
    for (int i1 = 0; i1 < 2; ++i1)
#pragma unroll
      for (int i2 = 0; i2 < 2; ++i2)
#pragma unroll
        for (int i3 = 0; i3 < 4; ++i3) po[i0][i1][i2][i3] = 0ULL;

  const unsigned long long ONE2  = 0x3F8000003F800000ULL;
  const unsigned long long MONE2 = 0xBF800000BF800000ULL;

  auto issueA = [&](int c, int buf) {
    uint32_t aB = sA0 + buf * A_BYTES;
#pragma unroll
    for (int i = 0; i < 5; ++i) {
      int task = tid + i * NTHR;
      if (task < 4 * A_NSLOT * 4) {
        int seg = task & 3;
        int s = (task >> 2) % A_NSLOT;
        int r = (task >> 2) / A_NSLOT;
        int gh = h0 - 1 + r;
        int w = w0 + s - 1;
        if ((unsigned)gh < (unsigned)HW && (unsigned)w < (unsigned)HW) {
          const __half* src = d_x16 +
              (((size_t)(b * HW + gh) * HW + w) * CH + c * 32 + seg * 8);
          cp16(aB + (uint32_t)(r * A_NSLOT + s) * A_SLOT + seg * 16, src);
        }
      }
    }
    cp_commit();
  };

  auto transform = [&](int buf) {
    const unsigned char* aB = sh + buf * A_BYTES;
#pragma unroll
    for (int it = 0; it < 2; ++it) {
      int item = tid + it * NTHR;
      int cp = item & 15;
      int tw = item >> 4;
      const unsigned char* base = aB + (uint32_t)(2 * tw) * A_SLOT + cp * 4;
      __half2 te[4][4];
#pragma unroll
      for (int j = 0; j < 4; ++j) {
        __half2 d0 = *(const __half2*)(base + (uint32_t)(0 * A_NSLOT + j) * A_SLOT);
        __half2 d1 = *(const __half2*)(base + (uint32_t)(1 * A_NSLOT + j) * A_SLOT);
        __half2 d2 = *(const __half2*)(base + (uint32_t)(2 * A_NSLOT + j) * A_SLOT);
        __half2 d3 = *(const __half2*)(base + (uint32_t)(3 * A_NSLOT + j) * A_SLOT);
        te[0][j] = __hsub2(d0, d2);
        te[1][j] = __hadd2(d1, d2);
        te[2][j] = __hsub2(d2, d1);
        te[3][j] = __hsub2(d1, d3);
      }
#pragma unroll
      for (int i2 = 0; i2 < 4; ++i2) {
        __half2 v0 = __hsub2(te[i2][0], te[i2][2]);
        __half2 v1 = __hadd2(te[i2][1], te[i2][2]);
        __half2 v2 = __hsub2(te[i2][2], te[i2][1]);
        __half2 v3 = __hsub2(te[i2][1], te[i2][3]);
        uint32_t vb = (uint32_t)((i2 * 4) * 32 + tw) * V_STR + cp * 4;
        *(__half2*)(sh + 2 * A_BYTES + vb)                 = v0;
        *(__half2*)(sh + 2 * A_BYTES + vb + 32 * V_STR)    = v1;
        *(__half2*)(sh + 2 * A_BYTES + vb + 2 * 32 * V_STR) = v2;
        *(__half2*)(sh + 2 * A_BYTES + vb + 3 * 32 * V_STR) = v3;
      }
    }
  };

  auto ldW = [&](int cg, int nu, int grp) -> uint2 {
    return *((const uint2*)d_WU +
             (((cg * 16 + nu) * 16 + wN8 * 2 + grp) * 32 + lane));
  };

  const float AT0[4] = {1.f, 1.f, 1.f, 0.f};
  const float AT1[4] = {0.f, 1.f, -1.f, -1.f};
  const float fz = 0.f;

  issueA(0, 0);

  for (int c = 0; c < 4; ++c) {
    if (c < 3) issueA(c + 1, (c + 1) & 1);
    if (c < 3) cp_wait1(); else cp_wait0();
    __syncthreads();

    transform(c & 1);
    __syncthreads();

    uint2 wc0 = ldW(c * 2, 0, 0), wc1 = ldW(c * 2, 0, 1);
    uint2 wn0, wn1;

#pragma unroll
    for (int nu = 0; nu < 16; ++nu) {
      float macc[2][2][4];
#pragma unroll
      for (int sub = 0; sub < 2; ++sub) {
        int ns = nu * 2 + sub;
        if (ns < 31) {
          int nn = ns + 1;
          wn0 = ldW(c * 2 + (nn & 1), nn >> 1, 0);
          wn1 = ldW(c * 2 + (nn & 1), nn >> 1, 1);
        }

        uint32_t afr[2][4];
#pragma unroll
        for (int mblk = 0; mblk < 2; ++mblk) {
          uint32_t addr = sV +
              (uint32_t)(nu * 32 + mblk * 16 + rsel) * V_STR
              + sub * 32 + csel * 16;
          asm volatile(
            "ldmatrix.sync.aligned.m8n8.x4.shared.b16 {%0,%1,%2,%3}, [%4];\n"
            : "=r"(afr[mblk][0]), "=r"(afr[mblk][1]),
              "=r"(afr[mblk][2]), "=r"(afr[mblk][3])
            : "r"(addr));
        }

        uint32_t bf[2][2] = {{wc0.x, wc0.y}, {wc1.x, wc1.y}};

#pragma unroll
        for (int mblk = 0; mblk < 2; ++mblk)
#pragma unroll
          for (int grp = 0; grp < 2; ++grp) {
            if (sub == 0)
              asm volatile(
                "mma.sync.aligned.m16n8k16.row.col.f32.f16.f16.f32 "
                "{%0,%1,%2,%3}, {%4,%5,%6,%7}, {%8,%9}, {%10,%10,%10,%10};\n"
                : "=f"(macc[mblk][grp][0]), "=f"(macc[mblk][grp][1]),
                  "=f"(macc[mblk][grp][2]), "=f"(macc[mblk][grp][3])
                : "r"(afr[mblk][0]), "r"(afr[mblk][1]),
                  "r"(afr[mblk][2]), "r"(afr[mblk][3]),
                  "r"(bf[grp][0]), "r"(bf[grp][1]), "f"(fz));
            else
              asm volatile(
                "mma.sync.aligned.m16n8k16.row.col.f32.f16.f16.f32 "
                "{%0,%1,%2,%3}, {%4,%5,%6,%7}, {%8,%9}, {%0,%1,%2,%3};\n"
                : "+f"(macc[mblk][grp][0]), "+f"(macc[mblk][grp][1]),
                  "+f"(macc[mblk][grp][2]), "+f"(macc[mblk][grp][3])
                : "r"(afr[mblk][0]), "r"(afr[mblk][1]),
                  "r"(afr[mblk][2]), "r"(afr[mblk][3]),
                  "r"(bf[grp][0]), "r"(bf[grp][1]));
          }
        if (ns < 31) { wc0 = wn0; wc1 = wn1; }
      }

      // ---- packed fold (FFMA2): pair over ji, signs are +/-1 ----
      const int nur = nu >> 2, nuc = nu & 3;
#pragma unroll
      for (int mblk = 0; mblk < 2; ++mblk)
#pragma unroll
        for (int grp = 0; grp < 2; ++grp)
#pragma unroll
          for (int gi = 0; gi < 2; ++gi) {
            unsigned long long mp;
            asm("mov.b64 %0, {%1,%2};" : "=l"(mp)
                : "r"(__float_as_uint(macc[mblk][grp][gi * 2 + 0])),
                  "r"(__float_as_uint(macc[mblk][grp][gi * 2 + 1])));
#pragma unroll
            for (int xx = 0; xx < 2; ++xx) {
              float cx = (xx == 0) ? AT0[nur] : AT1[nur];
              if (cx == 0.f) continue;
#pragma unroll
              for (int yy = 0; yy < 2; ++yy) {
                float cy = (yy == 0) ? AT0[nuc] : AT1[nuc];
                if (cy == 0.f) continue;
                unsigned long long cc = (cx * cy > 0.f) ? ONE2 : MONE2;
                asm("fma.rn.f32x2 %0, %1, %2, %0;"
                    : "+l"(po[mblk][grp][gi][xx * 2 + yy])
                    : "l"(mp), "l"(cc));
              }
            }
          }
    }
  }

  // ---- epilogue: unpack, bias, float2 stores ----
#pragma unroll
  for (int mblk = 0; mblk < 2; ++mblk)
#pragma unroll
    for (int grp = 0; grp < 2; ++grp) {
      int coB = wN8 * 16 + grp * 8 + 2 * q;
      float be0 = d_Beff[coB], be1 = d_Beff[coB + 1];
      float* ob0 = out + ((size_t)(b * CH + coB)) * HW * HW;
      float* ob1 = ob0 + (size_t)HW * HW;
#pragma unroll
      for (int gi = 0; gi < 2; ++gi) {
        int twp = mblk * 16 + g + gi * 8;
        int wpix = w0 + 2 * twp;
#pragma unroll
        for (int xx = 0; xx < 2; ++xx) {
          uint32_t a0, a1, b0, b1;
          asm("mov.b64 {%0,%1}, %2;" : "=r"(a0), "=r"(a1)
              : "l"(po[mblk][grp][gi][xx * 2 + 0]));
          asm("mov.b64 {%0,%1}, %2;" : "=r"(b0), "=r"(b1)
              : "l"(po[mblk][grp][gi][xx * 2 + 1]));
          float2 v0, v1;
          v0.x = __uint_as_float(a0) + be0;  // ji=0, yy=0
          v0.y = __uint_as_float(b0) + be0;  // ji=0, yy=1
          v1.x = __uint_as_float(a1) + be1;  // ji=1, yy=0
          v1.y = __uint_as_float(b1) + be1;  // ji=1, yy=1
          *(float2*)(ob0 + (size_t)(h0 + xx) * HW + wpix) = v0;
          *(float2*)(ob1 + (size_t)(h0 + xx) * HW + wpix) = v1;
        }
      }
    }
}

// ---------------------------------------------------------------------------
extern "C" void kernel_launch(void* const* d_in, const int* in_sizes, int n_in,
                              void* d_out, int out_size) {
  (void)in_sizes; (void)n_in; (void)out_size;
  const float* x = (const float*)d_in[0];
  const float* W = (const float*)d_in[1];
  const float* b = (const float*)d_in[2];
  float* out = (float*)d_out;

  dim3 gx(HW, NB);
  xprep_kernel<<<gx, 256>>>(x);
  wu_kernel<<<32, 256>>>(W, b);
  nop_kernel<<<1, 32>>>();   // profiler alignment: conv = launch position 3

  cudaFuncSetAttribute(conv_wino,
                       cudaFuncAttributeMaxDynamicSharedMemorySize, SM_TOTAL);
  dim3 grid(128, NB);   // (tile-row * w-half, b)
  conv_wino<<<grid, NTHR, SM_TOTAL>>>(out);
}